// round 1
// baseline (speedup 1.0000x reference)
#include <cuda_runtime.h>
#include <math.h>

#define EPS 1e-5f

// Shapes (fixed by the problem)
//  x : [16, 32, 112, 112]
//  h : [16, 192, 112, 112]
static const int HW = 112 * 112;   // 12544

// ---------------- scratch (device globals; no allocation allowed) ----------
__device__ float g_w1q[192 * 32];
__device__ float g_w2q[192 * 192 * 9];
__device__ float g_w3q[32 * 192];
__device__ float g_h1[16 * 192 * 12544];   // 154 MB
__device__ float g_h2[16 * 192 * 12544];   // 154 MB
__device__ float g_delta[3];
__device__ float g_alpha[3];

// ---------------- TWN ternarization: delta/alpha stats (deterministic) -----
__global__ void twn_stats(const float* __restrict__ w, int n, int slot) {
    __shared__ double sd[1024];
    __shared__ int    si[1024];
    __shared__ float  s_delta;
    int tid = threadIdx.x;

    double s = 0.0;
    for (int i = tid; i < n; i += 1024) s += (double)fabsf(w[i]);
    sd[tid] = s;
    __syncthreads();
    for (int off = 512; off > 0; off >>= 1) {
        if (tid < off) sd[tid] += sd[tid + off];
        __syncthreads();
    }
    if (tid == 0) s_delta = (float)(0.7 * sd[0] / (double)n);
    __syncthreads();
    float delta = s_delta;

    double s2 = 0.0; int c = 0;
    for (int i = tid; i < n; i += 1024) {
        float a = fabsf(w[i]);
        if (a > delta) { s2 += (double)a; c++; }
    }
    sd[tid] = s2; si[tid] = c;
    __syncthreads();
    for (int off = 512; off > 0; off >>= 1) {
        if (tid < off) { sd[tid] += sd[tid + off]; si[tid] += si[tid + off]; }
        __syncthreads();
    }
    if (tid == 0) {
        g_delta[slot] = delta;
        int cnt = si[0] < 1 ? 1 : si[0];
        g_alpha[slot] = (float)(sd[0] / (double)cnt);
    }
}

__global__ void twn_quant(const float* __restrict__ w, int n, int slot) {
    float* q = (slot == 0) ? g_w1q : (slot == 1) ? g_w2q : g_w3q;
    float delta = g_delta[slot];
    float alpha = g_alpha[slot];
    for (int i = blockIdx.x * blockDim.x + threadIdx.x; i < n;
         i += gridDim.x * blockDim.x) {
        float wv = w[i];
        q[i] = (fabsf(wv) > delta) ? copysignf(alpha, wv) : 0.0f;
    }
}

// ---------------- conv1: 1x1, 32->192, BN + ReLU6 --------------------------
// grid: (49 hw-tiles of 256, 6 co-chunks of 32, 16 batch), 256 thr
__global__ __launch_bounds__(256) void conv1_kernel(
    const float* __restrict__ x,
    const float* __restrict__ g1, const float* __restrict__ b1,
    const float* __restrict__ m1, const float* __restrict__ v1)
{
    __shared__ float xs[32 * 256];
    __shared__ float ws[32 * 32];
    int tid = threadIdx.x;
    int b   = blockIdx.z;
    int co0 = blockIdx.y * 32;
    int hw0 = blockIdx.x * 256;

    const float* xb = x + (size_t)b * 32 * HW + hw0;
#pragma unroll
    for (int i = 0; i < 32; i++) xs[i * 256 + tid] = xb[(size_t)i * HW + tid];
    for (int i = tid; i < 32 * 32; i += 256) ws[i] = g_w1q[co0 * 32 + i];
    __syncthreads();

    int c0 = (tid >> 6) * 8;     // 0,8,16,24
    int p0 = tid & 63;
    float acc[8][4] = {};

#pragma unroll 8
    for (int ci = 0; ci < 32; ci++) {
        float xv[4];
#pragma unroll
        for (int k = 0; k < 4; k++) xv[k] = xs[ci * 256 + p0 + 64 * k];
#pragma unroll
        for (int j = 0; j < 8; j++) {
            float wv = ws[(c0 + j) * 32 + ci];
#pragma unroll
            for (int k = 0; k < 4; k++) acc[j][k] = fmaf(wv, xv[k], acc[j][k]);
        }
    }

#pragma unroll
    for (int j = 0; j < 8; j++) {
        int c = co0 + c0 + j;
        float sc = g1[c] * rsqrtf(v1[c] + EPS);
        float sh = b1[c] - m1[c] * sc;
        size_t base = ((size_t)b * 192 + c) * HW + hw0 + p0;
#pragma unroll
        for (int k = 0; k < 4; k++) {
            float y = fmaf(acc[j][k], sc, sh);
            y = fminf(fmaxf(y, 0.0f), 6.0f);
            g_h1[base + 64 * k] = y;
        }
    }
}

// ---------------- conv2: 3x3 dense, 192->192, pad 1, BN + ReLU6 ------------
// Output tile: 64 co x (8 rows x 16 cols). grid (7, 14, 16*3). 256 thr.
// Per thread: 8 co x (2y x 2x) = 32 accumulators.
__global__ __launch_bounds__(256) void conv2_kernel(
    const float* __restrict__ g2, const float* __restrict__ b2,
    const float* __restrict__ m2, const float* __restrict__ v2)
{
    __shared__ float in_s[16 * 10 * 18];   // 2880 f = 11520 B
    __shared__ float ws[64 * 144];         // 9216 f = 36864 B
    int tid = threadIdx.x;
    int bz  = blockIdx.z;
    int b   = bz / 3;
    int co0 = (bz % 3) * 64;
    int y0g = blockIdx.y * 8;
    int x0g = blockIdx.x * 16;

    int c0 = (tid >> 5) * 8;          // 8 co per thread
    int pid = tid & 31;
    int x0 = (pid & 7) * 2;
    int y0 = (pid >> 3) * 2;

    float acc[8][4] = {};

    for (int ci0 = 0; ci0 < 192; ci0 += 16) {
        __syncthreads();
        // weights: ws[co_l][ci_l*9 + k]
        for (int i = tid; i < 64 * 144; i += 256) {
            int co_l = i / 144; int r = i - co_l * 144;
            ws[i] = g_w2q[(size_t)(co0 + co_l) * 1728 + ci0 * 9 + r];
        }
        // input halo tile: 16 ch x 10 rows x 18 cols
        for (int i = tid; i < 16 * 180; i += 256) {
            int ci_l = i / 180; int rem = i - ci_l * 180;
            int r = rem / 18, c = rem - r * 18;
            int gy = y0g + r - 1, gx = x0g + c - 1;
            float v = 0.0f;
            if ((unsigned)gy < 112u && (unsigned)gx < 112u)
                v = g_h1[(((size_t)b * 192 + ci0 + ci_l) * 112 + gy) * 112 + gx];
            in_s[i] = v;
        }
        __syncthreads();

#pragma unroll 2
        for (int ci = 0; ci < 16; ci++) {
#pragma unroll
            for (int ky = 0; ky < 3; ky++) {
#pragma unroll
                for (int kx = 0; kx < 3; kx++) {
                    float iv[4];
                    int ib = ci * 180 + (y0 + ky) * 18 + x0 + kx;
                    iv[0] = in_s[ib];
                    iv[1] = in_s[ib + 1];
                    iv[2] = in_s[ib + 18];
                    iv[3] = in_s[ib + 19];
#pragma unroll
                    for (int j = 0; j < 8; j++) {
                        float wv = ws[(c0 + j) * 144 + ci * 9 + ky * 3 + kx];
#pragma unroll
                        for (int k = 0; k < 4; k++)
                            acc[j][k] = fmaf(wv, iv[k], acc[j][k]);
                    }
                }
            }
        }
    }

#pragma unroll
    for (int j = 0; j < 8; j++) {
        int c = co0 + c0 + j;
        float sc = g2[c] * rsqrtf(v2[c] + EPS);
        float sh = b2[c] - m2[c] * sc;
#pragma unroll
        for (int a = 0; a < 2; a++) {
#pragma unroll
            for (int e = 0; e < 2; e++) {
                float y = fmaf(acc[j][a * 2 + e], sc, sh);
                y = fminf(fmaxf(y, 0.0f), 6.0f);
                g_h2[(((size_t)b * 192 + c) * 112 + y0g + y0 + a) * 112 +
                     x0g + x0 + e] = y;
            }
        }
    }
}

// ---------------- conv3: 1x1, 192->32, BN + residual -----------------------
// grid: (49 hw-tiles, 16 batch), 256 thr
__global__ __launch_bounds__(256) void conv3_kernel(
    const float* __restrict__ x,
    const float* __restrict__ g3, const float* __restrict__ b3,
    const float* __restrict__ m3, const float* __restrict__ v3,
    float* __restrict__ out)
{
    __shared__ float hs[16 * 256];
    __shared__ float ws[32 * 192];
    int tid = threadIdx.x;
    int b   = blockIdx.y;
    int hw0 = blockIdx.x * 256;

    for (int i = tid; i < 32 * 192; i += 256) ws[i] = g_w3q[i];

    int c0 = (tid >> 6) * 8;   // 0,8,16,24 (32 co total)
    int p0 = tid & 63;
    float acc[8][4] = {};

    for (int ci0 = 0; ci0 < 192; ci0 += 16) {
        __syncthreads();
#pragma unroll
        for (int i = 0; i < 16; i++)
            hs[i * 256 + tid] =
                g_h2[((size_t)b * 192 + ci0 + i) * HW + hw0 + tid];
        __syncthreads();
#pragma unroll 4
        for (int ci = 0; ci < 16; ci++) {
            float xv[4];
#pragma unroll
            for (int k = 0; k < 4; k++) xv[k] = hs[ci * 256 + p0 + 64 * k];
#pragma unroll
            for (int j = 0; j < 8; j++) {
                float wv = ws[(c0 + j) * 192 + ci0 + ci];
#pragma unroll
                for (int k = 0; k < 4; k++)
                    acc[j][k] = fmaf(wv, xv[k], acc[j][k]);
            }
        }
    }

#pragma unroll
    for (int j = 0; j < 8; j++) {
        int c = c0 + j;
        float sc = g3[c] * rsqrtf(v3[c] + EPS);
        float sh = b3[c] - m3[c] * sc;
        size_t base = ((size_t)b * 32 + c) * HW + hw0 + p0;
#pragma unroll
        for (int k = 0; k < 4; k++) {
            float y = fmaf(acc[j][k], sc, sh) + x[base + 64 * k];
            out[base + 64 * k] = y;
        }
    }
}

// ---------------- launch ----------------------------------------------------
extern "C" void kernel_launch(void* const* d_in, const int* in_sizes, int n_in,
                              void* d_out, int out_size) {
    const float* x  = (const float*)d_in[0];
    const float* w1 = (const float*)d_in[1];
    const float* g1 = (const float*)d_in[2];
    const float* b1 = (const float*)d_in[3];
    const float* m1 = (const float*)d_in[4];
    const float* v1 = (const float*)d_in[5];
    const float* w2 = (const float*)d_in[6];
    const float* g2 = (const float*)d_in[7];
    const float* b2 = (const float*)d_in[8];
    const float* m2 = (const float*)d_in[9];
    const float* v2 = (const float*)d_in[10];
    const float* w3 = (const float*)d_in[11];
    const float* g3 = (const float*)d_in[12];
    const float* b3 = (const float*)d_in[13];
    const float* m3 = (const float*)d_in[14];
    const float* v3 = (const float*)d_in[15];
    float* out = (float*)d_out;

    // ternarize the three weight tensors
    twn_stats<<<1, 1024>>>(w1, 192 * 32, 0);
    twn_stats<<<1, 1024>>>(w2, 192 * 192 * 9, 1);
    twn_stats<<<1, 1024>>>(w3, 32 * 192, 2);
    twn_quant<<<24, 256>>>(w1, 192 * 32, 0);
    twn_quant<<<1296, 256>>>(w2, 192 * 192 * 9, 1);
    twn_quant<<<24, 256>>>(w3, 32 * 192, 2);

    // expand -> 3x3 -> project(+residual)
    conv1_kernel<<<dim3(49, 6, 16), 256>>>(x, g1, b1, m1, v1);
    conv2_kernel<<<dim3(7, 14, 48), 256>>>(g2, b2, m2, v2);
    conv3_kernel<<<dim3(49, 16), 256>>>(x, g3, b3, m3, v3, out);
}

// round 2
// speedup vs baseline: 1.0001x; 1.0001x over previous
#include <cuda_runtime.h>
#include <math.h>

#define EPS 1e-5f

// Shapes (fixed by the problem)
//  x : [16, 32, 112, 112]
//  h : [16, 192, 112, 112]
static const int HW = 112 * 112;   // 12544

// ---------------- scratch (device globals; no allocation allowed) ----------
__device__ float g_w1q[192 * 32];
__device__ float g_w2q[192 * 192 * 9];
__device__ float g_w3q[32 * 192];
__device__ float g_h1[16 * 192 * 12544];   // 154 MB
__device__ float g_h2[16 * 192 * 12544];   // 154 MB
__device__ float g_delta[3];
__device__ float g_alpha[3];

// ---------------- TWN ternarization: delta/alpha stats (deterministic) -----
__global__ void twn_stats(const float* __restrict__ w, int n, int slot) {
    __shared__ double sd[1024];
    __shared__ int    si[1024];
    __shared__ float  s_delta;
    int tid = threadIdx.x;

    double s = 0.0;
    for (int i = tid; i < n; i += 1024) s += (double)fabsf(w[i]);
    sd[tid] = s;
    __syncthreads();
    for (int off = 512; off > 0; off >>= 1) {
        if (tid < off) sd[tid] += sd[tid + off];
        __syncthreads();
    }
    if (tid == 0) s_delta = (float)(0.7 * sd[0] / (double)n);
    __syncthreads();
    float delta = s_delta;

    double s2 = 0.0; int c = 0;
    for (int i = tid; i < n; i += 1024) {
        float a = fabsf(w[i]);
        if (a > delta) { s2 += (double)a; c++; }
    }
    sd[tid] = s2; si[tid] = c;
    __syncthreads();
    for (int off = 512; off > 0; off >>= 1) {
        if (tid < off) { sd[tid] += sd[tid + off]; si[tid] += si[tid + off]; }
        __syncthreads();
    }
    if (tid == 0) {
        g_delta[slot] = delta;
        int cnt = si[0] < 1 ? 1 : si[0];
        g_alpha[slot] = (float)(sd[0] / (double)cnt);
    }
}

__global__ void twn_quant(const float* __restrict__ w, int n, int slot) {
    float* q = (slot == 0) ? g_w1q : (slot == 1) ? g_w2q : g_w3q;
    float delta = g_delta[slot];
    float alpha = g_alpha[slot];
    for (int i = blockIdx.x * blockDim.x + threadIdx.x; i < n;
         i += gridDim.x * blockDim.x) {
        float wv = w[i];
        q[i] = (fabsf(wv) > delta) ? copysignf(alpha, wv) : 0.0f;
    }
}

// ---------------- conv1: 1x1, 32->192, BN + ReLU6 --------------------------
// grid: (49 hw-tiles of 256, 6 co-chunks of 32, 16 batch), 256 thr
__global__ __launch_bounds__(256) void conv1_kernel(
    const float* __restrict__ x,
    const float* __restrict__ g1, const float* __restrict__ b1,
    const float* __restrict__ m1, const float* __restrict__ v1)
{
    __shared__ float xs[32 * 256];
    __shared__ float ws[32 * 32];
    int tid = threadIdx.x;
    int b   = blockIdx.z;
    int co0 = blockIdx.y * 32;
    int hw0 = blockIdx.x * 256;

    const float* xb = x + (size_t)b * 32 * HW + hw0;
#pragma unroll
    for (int i = 0; i < 32; i++) xs[i * 256 + tid] = xb[(size_t)i * HW + tid];
    for (int i = tid; i < 32 * 32; i += 256) ws[i] = g_w1q[co0 * 32 + i];
    __syncthreads();

    int c0 = (tid >> 6) * 8;     // 0,8,16,24
    int p0 = tid & 63;
    float acc[8][4] = {};

#pragma unroll 8
    for (int ci = 0; ci < 32; ci++) {
        float xv[4];
#pragma unroll
        for (int k = 0; k < 4; k++) xv[k] = xs[ci * 256 + p0 + 64 * k];
#pragma unroll
        for (int j = 0; j < 8; j++) {
            float wv = ws[(c0 + j) * 32 + ci];
#pragma unroll
            for (int k = 0; k < 4; k++) acc[j][k] = fmaf(wv, xv[k], acc[j][k]);
        }
    }

#pragma unroll
    for (int j = 0; j < 8; j++) {
        int c = co0 + c0 + j;
        float sc = g1[c] * rsqrtf(v1[c] + EPS);
        float sh = b1[c] - m1[c] * sc;
        size_t base = ((size_t)b * 192 + c) * HW + hw0 + p0;
#pragma unroll
        for (int k = 0; k < 4; k++) {
            float y = fmaf(acc[j][k], sc, sh);
            y = fminf(fmaxf(y, 0.0f), 6.0f);
            g_h1[base + 64 * k] = y;
        }
    }
}

// ---------------- conv2: 3x3 dense, 192->192, pad 1, BN + ReLU6 ------------
// Output tile: 64 co x (8 rows x 16 cols). grid (7, 14, 16*3). 256 thr.
// Per thread: 8 co x (2y x 2x) = 32 accumulators.
__global__ __launch_bounds__(256) void conv2_kernel(
    const float* __restrict__ g2, const float* __restrict__ b2,
    const float* __restrict__ m2, const float* __restrict__ v2)
{
    __shared__ float in_s[16 * 10 * 18];   // 2880 f = 11520 B
    __shared__ float ws[64 * 144];         // 9216 f = 36864 B
    int tid = threadIdx.x;
    int bz  = blockIdx.z;
    int b   = bz / 3;
    int co0 = (bz % 3) * 64;
    int y0g = blockIdx.y * 8;
    int x0g = blockIdx.x * 16;

    int c0 = (tid >> 5) * 8;          // 8 co per thread
    int pid = tid & 31;
    int x0 = (pid & 7) * 2;
    int y0 = (pid >> 3) * 2;

    float acc[8][4] = {};

    for (int ci0 = 0; ci0 < 192; ci0 += 16) {
        __syncthreads();
        // weights: ws[co_l][ci_l*9 + k]
        for (int i = tid; i < 64 * 144; i += 256) {
            int co_l = i / 144; int r = i - co_l * 144;
            ws[i] = g_w2q[(size_t)(co0 + co_l) * 1728 + ci0 * 9 + r];
        }
        // input halo tile: 16 ch x 10 rows x 18 cols
        for (int i = tid; i < 16 * 180; i += 256) {
            int ci_l = i / 180; int rem = i - ci_l * 180;
            int r = rem / 18, c = rem - r * 18;
            int gy = y0g + r - 1, gx = x0g + c - 1;
            float v = 0.0f;
            if ((unsigned)gy < 112u && (unsigned)gx < 112u)
                v = g_h1[(((size_t)b * 192 + ci0 + ci_l) * 112 + gy) * 112 + gx];
            in_s[i] = v;
        }
        __syncthreads();

#pragma unroll 2
        for (int ci = 0; ci < 16; ci++) {
#pragma unroll
            for (int ky = 0; ky < 3; ky++) {
#pragma unroll
                for (int kx = 0; kx < 3; kx++) {
                    float iv[4];
                    int ib = ci * 180 + (y0 + ky) * 18 + x0 + kx;
                    iv[0] = in_s[ib];
                    iv[1] = in_s[ib + 1];
                    iv[2] = in_s[ib + 18];
                    iv[3] = in_s[ib + 19];
#pragma unroll
                    for (int j = 0; j < 8; j++) {
                        float wv = ws[(c0 + j) * 144 + ci * 9 + ky * 3 + kx];
#pragma unroll
                        for (int k = 0; k < 4; k++)
                            acc[j][k] = fmaf(wv, iv[k], acc[j][k]);
                    }
                }
            }
        }
    }

#pragma unroll
    for (int j = 0; j < 8; j++) {
        int c = co0 + c0 + j;
        float sc = g2[c] * rsqrtf(v2[c] + EPS);
        float sh = b2[c] - m2[c] * sc;
#pragma unroll
        for (int a = 0; a < 2; a++) {
#pragma unroll
            for (int e = 0; e < 2; e++) {
                float y = fmaf(acc[j][a * 2 + e], sc, sh);
                y = fminf(fmaxf(y, 0.0f), 6.0f);
                g_h2[(((size_t)b * 192 + c) * 112 + y0g + y0 + a) * 112 +
                     x0g + x0 + e] = y;
            }
        }
    }
}

// ---------------- conv3: 1x1, 192->32, BN + residual -----------------------
// grid: (49 hw-tiles, 16 batch), 256 thr
__global__ __launch_bounds__(256) void conv3_kernel(
    const float* __restrict__ x,
    const float* __restrict__ g3, const float* __restrict__ b3,
    const float* __restrict__ m3, const float* __restrict__ v3,
    float* __restrict__ out)
{
    __shared__ float hs[16 * 256];
    __shared__ float ws[32 * 192];
    int tid = threadIdx.x;
    int b   = blockIdx.y;
    int hw0 = blockIdx.x * 256;

    for (int i = tid; i < 32 * 192; i += 256) ws[i] = g_w3q[i];

    int c0 = (tid >> 6) * 8;   // 0,8,16,24 (32 co total)
    int p0 = tid & 63;
    float acc[8][4] = {};

    for (int ci0 = 0; ci0 < 192; ci0 += 16) {
        __syncthreads();
#pragma unroll
        for (int i = 0; i < 16; i++)
            hs[i * 256 + tid] =
                g_h2[((size_t)b * 192 + ci0 + i) * HW + hw0 + tid];
        __syncthreads();
#pragma unroll 4
        for (int ci = 0; ci < 16; ci++) {
            float xv[4];
#pragma unroll
            for (int k = 0; k < 4; k++) xv[k] = hs[ci * 256 + p0 + 64 * k];
#pragma unroll
            for (int j = 0; j < 8; j++) {
                float wv = ws[(c0 + j) * 192 + ci0 + ci];
#pragma unroll
                for (int k = 0; k < 4; k++)
                    acc[j][k] = fmaf(wv, xv[k], acc[j][k]);
            }
        }
    }

#pragma unroll
    for (int j = 0; j < 8; j++) {
        int c = c0 + j;
        float sc = g3[c] * rsqrtf(v3[c] + EPS);
        float sh = b3[c] - m3[c] * sc;
        size_t base = ((size_t)b * 32 + c) * HW + hw0 + p0;
#pragma unroll
        for (int k = 0; k < 4; k++) {
            float y = fmaf(acc[j][k], sc, sh) + x[base + 64 * k];
            out[base + 64 * k] = y;
        }
    }
}

// ---------------- launch ----------------------------------------------------
extern "C" void kernel_launch(void* const* d_in, const int* in_sizes, int n_in,
                              void* d_out, int out_size) {
    const float* x  = (const float*)d_in[0];
    const float* w1 = (const float*)d_in[1];
    const float* g1 = (const float*)d_in[2];
    const float* b1 = (const float*)d_in[3];
    const float* m1 = (const float*)d_in[4];
    const float* v1 = (const float*)d_in[5];
    const float* w2 = (const float*)d_in[6];
    const float* g2 = (const float*)d_in[7];
    const float* b2 = (const float*)d_in[8];
    const float* m2 = (const float*)d_in[9];
    const float* v2 = (const float*)d_in[10];
    const float* w3 = (const float*)d_in[11];
    const float* g3 = (const float*)d_in[12];
    const float* b3 = (const float*)d_in[13];
    const float* m3 = (const float*)d_in[14];
    const float* v3 = (const float*)d_in[15];
    float* out = (float*)d_out;

    // ternarize the three weight tensors
    twn_stats<<<1, 1024>>>(w1, 192 * 32, 0);
    twn_stats<<<1, 1024>>>(w2, 192 * 192 * 9, 1);
    twn_stats<<<1, 1024>>>(w3, 32 * 192, 2);
    twn_quant<<<24, 256>>>(w1, 192 * 32, 0);
    twn_quant<<<1296, 256>>>(w2, 192 * 192 * 9, 1);
    twn_quant<<<24, 256>>>(w3, 32 * 192, 2);

    // expand -> 3x3 -> project(+residual)
    conv1_kernel<<<dim3(49, 6, 16), 256>>>(x, g1, b1, m1, v1);
    conv2_kernel<<<dim3(7, 14, 48), 256>>>(g2, b2, m2, v2);
    conv3_kernel<<<dim3(49, 16), 256>>>(x, g3, b3, m3, v3, out);
}

// round 4
// speedup vs baseline: 6.1981x; 6.1975x over previous
#include <cuda_runtime.h>
#include <cuda_fp16.h>
#include <math.h>
#include <stdint.h>

#define EPS 1e-5f
static const int HW = 112 * 112;      // 12544
static const int PPIX = 13184;        // padded pixels per image (114*114=12996 -> 13184)

// ---------------- scratch (device globals; zero-initialized) ---------------
__device__ float  g_w1q[192 * 32];                  // ±alpha1 fp32
__device__ __half g_w2r[9 * 192 * 192];             // ±1 fp16, [shift][co][ci]
__device__ __half g_w3r[32 * 192];                  // ±1 fp16, [co][ci]
__device__ __half g_h1p[(size_t)16 * PPIX * 192];   // padded NHWC fp16 (~81MB)
__device__ __half g_h2[(size_t)16 * 12544 * 192];   // NHWC fp16 (~77MB)
__device__ float  g_delta[3];
__device__ float  g_alpha[3];
__device__ double g_partd[256];
__device__ int    g_parti[256];

// ---------------- helpers ----------------------------------------------------
__device__ __forceinline__ uint32_t smem_u32(const void* p) {
    uint32_t a;
    asm("{ .reg .u64 t; cvta.to.shared.u64 t, %1; cvt.u32.u64 %0, t; }"
        : "=r"(a) : "l"(p));
    return a;
}
#define SWZ(o) ((o) ^ (((o) >> 3) & 0x70))

#define CP_ASYNC16(saddr, gaddr) \
    asm volatile("cp.async.cg.shared.global [%0], [%1], 16;" \
        :: "r"(saddr), "l"(gaddr) : "memory")
#define CP_COMMIT() asm volatile("cp.async.commit_group;" ::: "memory")
#define CP_WAIT1()  asm volatile("cp.async.wait_group 1;" ::: "memory")

__device__ __forceinline__ void ldsm4(uint32_t a, uint32_t& r0, uint32_t& r1,
                                      uint32_t& r2, uint32_t& r3) {
    asm volatile("ldmatrix.sync.aligned.m8n8.x4.shared.b16 {%0,%1,%2,%3}, [%4];"
        : "=r"(r0), "=r"(r1), "=r"(r2), "=r"(r3) : "r"(a));
}
__device__ __forceinline__ void ldsm2(uint32_t a, uint32_t& r0, uint32_t& r1) {
    asm volatile("ldmatrix.sync.aligned.m8n8.x2.shared.b16 {%0,%1}, [%2];"
        : "=r"(r0), "=r"(r1) : "r"(a));
}
__device__ __forceinline__ void mma16816(float* c, uint32_t a0, uint32_t a1,
                                         uint32_t a2, uint32_t a3,
                                         uint32_t b0, uint32_t b1) {
    asm volatile(
        "mma.sync.aligned.m16n8k16.row.col.f32.f16.f16.f32 "
        "{%0,%1,%2,%3}, {%4,%5,%6,%7}, {%8,%9}, {%0,%1,%2,%3};"
        : "+f"(c[0]), "+f"(c[1]), "+f"(c[2]), "+f"(c[3])
        : "r"(a0), "r"(a1), "r"(a2), "r"(a3), "r"(b0), "r"(b1));
}

// ---------------- TWN stats: 2-stage deterministic reduction ---------------
__global__ void stats_abs_part(const float* __restrict__ w, int n) {
    __shared__ double sd[256];
    int tid = threadIdx.x;
    int g = blockIdx.x * 256 + tid, stride = gridDim.x * 256;
    double s = 0.0;
    for (int i = g; i < n; i += stride) s += (double)fabsf(w[i]);
    sd[tid] = s; __syncthreads();
    for (int o = 128; o > 0; o >>= 1) {
        if (tid < o) sd[tid] += sd[tid + o];
        __syncthreads();
    }
    if (tid == 0) g_partd[blockIdx.x] = sd[0];
}
__global__ void stats_delta_fin(int G, int n, int slot) {
    __shared__ double sd[256];
    int tid = threadIdx.x;
    sd[tid] = (tid < G) ? g_partd[tid] : 0.0; __syncthreads();
    for (int o = 128; o > 0; o >>= 1) {
        if (tid < o) sd[tid] += sd[tid + o];
        __syncthreads();
    }
    if (tid == 0) g_delta[slot] = (float)(0.7 * sd[0] / (double)n);
}
__global__ void stats_alpha_part(const float* __restrict__ w, int n, int slot) {
    __shared__ double sd[256];
    __shared__ int    si[256];
    int tid = threadIdx.x;
    int g = blockIdx.x * 256 + tid, stride = gridDim.x * 256;
    float delta = g_delta[slot];
    double s = 0.0; int c = 0;
    for (int i = g; i < n; i += stride) {
        float a = fabsf(w[i]);
        if (a > delta) { s += (double)a; c++; }
    }
    sd[tid] = s; si[tid] = c; __syncthreads();
    for (int o = 128; o > 0; o >>= 1) {
        if (tid < o) { sd[tid] += sd[tid + o]; si[tid] += si[tid + o]; }
        __syncthreads();
    }
    if (tid == 0) { g_partd[blockIdx.x] = sd[0]; g_parti[blockIdx.x] = si[0]; }
}
__global__ void stats_alpha_fin(int G, int slot) {
    __shared__ double sd[256];
    __shared__ int    si[256];
    int tid = threadIdx.x;
    sd[tid] = (tid < G) ? g_partd[tid] : 0.0;
    si[tid] = (tid < G) ? g_parti[tid] : 0;
    __syncthreads();
    for (int o = 128; o > 0; o >>= 1) {
        if (tid < o) { sd[tid] += sd[tid + o]; si[tid] += si[tid + o]; }
        __syncthreads();
    }
    if (tid == 0) {
        int cnt = si[0] < 1 ? 1 : si[0];
        g_alpha[slot] = (float)(sd[0] / (double)cnt);
    }
}

__global__ void prep_w1(const float* __restrict__ w) {
    float delta = g_delta[0], alpha = g_alpha[0];
    for (int i = blockIdx.x * blockDim.x + threadIdx.x; i < 192 * 32;
         i += gridDim.x * blockDim.x) {
        float wv = w[i];
        g_w1q[i] = (fabsf(wv) > delta) ? copysignf(alpha, wv) : 0.0f;
    }
}
__global__ void prep_w2(const float* __restrict__ w) {
    float delta = g_delta[1];
    int n = 192 * 192 * 9;
    for (int i = blockIdx.x * blockDim.x + threadIdx.x; i < n;
         i += gridDim.x * blockDim.x) {
        int co = i / 1728; int rem = i - co * 1728;
        int ci = rem / 9;  int kk = rem - ci * 9;
        float wv = w[i];
        float q = (fabsf(wv) > delta) ? (wv > 0.0f ? 1.0f : -1.0f) : 0.0f;
        g_w2r[((size_t)kk * 192 + co) * 192 + ci] = __float2half_rn(q);
    }
}
__global__ void prep_w3(const float* __restrict__ w) {
    float delta = g_delta[2];
    for (int i = blockIdx.x * blockDim.x + threadIdx.x; i < 32 * 192;
         i += gridDim.x * blockDim.x) {
        float wv = w[i];
        float q = (fabsf(wv) > delta) ? (wv > 0.0f ? 1.0f : -1.0f) : 0.0f;
        g_w3r[i] = __float2half_rn(q);
    }
}

// ---------------- conv1: 1x1, 32->192, BN + ReLU6 (SIMT fp32) --------------
__global__ __launch_bounds__(256) void conv1_kernel(
    const float* __restrict__ x,
    const float* __restrict__ g1, const float* __restrict__ b1,
    const float* __restrict__ m1, const float* __restrict__ v1)
{
    __shared__ float xs[32 * 256];
    __shared__ float ws[32 * 32];
    int tid = threadIdx.x;
    int b   = blockIdx.z;
    int co0 = blockIdx.y * 32;
    int hw0 = blockIdx.x * 256;

    const float* xb = x + (size_t)b * 32 * HW + hw0;
#pragma unroll
    for (int i = 0; i < 32; i++) xs[i * 256 + tid] = xb[(size_t)i * HW + tid];
    for (int i = tid; i < 32 * 32; i += 256) ws[i] = g_w1q[co0 * 32 + i];
    __syncthreads();

    int c0 = (tid >> 6) * 8;
    int p0 = tid & 63;
    float acc[8][4] = {};

#pragma unroll 8
    for (int ci = 0; ci < 32; ci++) {
        float xv[4];
#pragma unroll
        for (int k = 0; k < 4; k++) xv[k] = xs[ci * 256 + p0 + 64 * k];
#pragma unroll
        for (int j = 0; j < 8; j++) {
            float wv = ws[(c0 + j) * 32 + ci];
#pragma unroll
            for (int k = 0; k < 4; k++) acc[j][k] = fmaf(wv, xv[k], acc[j][k]);
        }
    }

    float sc[8], sh[8];
#pragma unroll
    for (int j = 0; j < 8; j++) {
        int c = co0 + c0 + j;
        float is = rsqrtf(v1[c] + EPS);
        sc[j] = g1[c] * is;
        sh[j] = b1[c] - m1[c] * g1[c] * is;
    }

    __half* h1b = g_h1p + (size_t)b * PPIX * 192;
#pragma unroll
    for (int k = 0; k < 4; k++) {
        int pu = hw0 + p0 + 64 * k;
        int y = pu / 112, xx = pu - y * 112;
        int pp = (y + 1) * 114 + (xx + 1);
        unsigned short hs[8];
#pragma unroll
        for (int j = 0; j < 8; j++) {
            float yv = fmaf(acc[j][k], sc[j], sh[j]);
            yv = fminf(fmaxf(yv, 0.0f), 6.0f);
            hs[j] = __half_as_ushort(__float2half_rn(yv));
        }
        uint4 pk;
        pk.x = (uint32_t)hs[0] | ((uint32_t)hs[1] << 16);
        pk.y = (uint32_t)hs[2] | ((uint32_t)hs[3] << 16);
        pk.z = (uint32_t)hs[4] | ((uint32_t)hs[5] << 16);
        pk.w = (uint32_t)hs[6] | ((uint32_t)hs[7] << 16);
        *(uint4*)(h1b + (size_t)pp * 192 + co0 + c0) = pk;
    }
}

// ---------------- conv2: 3x3 as 9 shift-GEMMs (HMMA mma.sync) --------------
// BM=128 padded pixels, BN=192, K = 9 shifts x 3 chunks of 64.
// 512 thr / 16 warps: warp grid 2(M) x 8(N) -> warp tile 64 x 24.
// SMEM: bn 1536B @0 | A0 @2048 | A1 @18432 | B0 @34816 | B1 @59392
#define C2_A0 2048
#define C2_B0 34816
#define C2_SMEM (2048 + 2 * 16384 + 2 * 24576 + 1024)

__global__ __launch_bounds__(512, 1) void conv2_mma(
    const float* __restrict__ g2, const float* __restrict__ b2,
    const float* __restrict__ m2, const float* __restrict__ v2)
{
    extern __shared__ char dsm[];
    uint32_t sb = (smem_u32(dsm) + 1023u) & ~1023u;
    char* sbase = dsm + (sb - smem_u32(dsm));
    float* bnS = (float*)sbase;

    int tid = threadIdx.x, wid = tid >> 5, lane = tid & 31;
    int img   = blockIdx.y;
    int pbase = 115 + blockIdx.x * 128;

    float alpha2 = g_alpha[1];
    for (int c = tid; c < 192; c += 512) {
        float is = rsqrtf(v2[c] + EPS);
        bnS[c]       = alpha2 * g2[c] * is;
        bnS[192 + c] = b2[c] - m2[c] * g2[c] * is;
    }

    const __half* h1i = g_h1p + (size_t)img * PPIX * 192;

    // per-chunk loader (cp.async)
    auto load_chunk = [&](int chunk) {
        int sh = chunk / 3, ch = chunk - sh * 3;
        int soff = (sh / 3 - 1) * 114 + (sh % 3 - 1);
        const __half* ain = h1i + (size_t)(pbase + soff) * 192 + ch * 64;
        const __half* bw  = g_w2r + (size_t)sh * 36864 + (size_t)ch * 64;
        uint32_t sA = sb + C2_A0 + (chunk & 1) * 16384;
        uint32_t sB = sb + C2_B0 + (chunk & 1) * 24576;
#pragma unroll
        for (int p = 0; p < 2; p++) {
            int lin = p * 512 + tid;
            int row = lin >> 3, c16 = lin & 7;
            CP_ASYNC16(sA + SWZ(row * 128 + c16 * 16),
                       (const char*)(ain + (size_t)row * 192) + c16 * 16);
        }
#pragma unroll
        for (int p = 0; p < 3; p++) {
            int lin = p * 512 + tid;
            int row = lin >> 3, c16 = lin & 7;
            CP_ASYNC16(sB + SWZ(row * 128 + c16 * 16),
                       (const char*)(bw + (size_t)row * 192) + c16 * 16);
        }
    };

    int wm = (wid >> 3) * 64;     // 0 or 64
    int wn = (wid & 7) * 24;      // 0..168

    float acc[4][3][4];
#pragma unroll
    for (int a = 0; a < 4; a++)
#pragma unroll
        for (int b = 0; b < 3; b++)
#pragma unroll
            for (int c = 0; c < 4; c++) acc[a][b][c] = 0.0f;

    load_chunk(0);
    CP_COMMIT();

    for (int c = 0; c < 27; c++) {
        if (c + 1 < 27) load_chunk(c + 1);
        CP_COMMIT();
        CP_WAIT1();
        __syncthreads();

        uint32_t sA = sb + C2_A0 + (c & 1) * 16384;
        uint32_t sB = sb + C2_B0 + (c & 1) * 24576;
#pragma unroll
        for (int kk = 0; kk < 4; kk++) {
            uint32_t bf[3][2];
#pragma unroll
            for (int ni = 0; ni < 3; ni++) {
                uint32_t a = sB + SWZ((wn + ni * 8 + (lane & 7)) * 128 +
                                      (kk * 16 + ((lane >> 3) & 1) * 8) * 2);
                ldsm2(a, bf[ni][0], bf[ni][1]);
            }
            uint32_t af[4][4];
#pragma unroll
            for (int mi = 0; mi < 4; mi++) {
                int m_loc = wm + mi * 16 + (lane & 7) + ((lane >> 3) & 1) * 8;
                int kh = kk * 16 + (lane >> 4) * 8;
                uint32_t a = sA + SWZ(m_loc * 128 + kh * 2);
                ldsm4(a, af[mi][0], af[mi][1], af[mi][2], af[mi][3]);
            }
#pragma unroll
            for (int mi = 0; mi < 4; mi++)
#pragma unroll
                for (int ni = 0; ni < 3; ni++)
                    mma16816(acc[mi][ni], af[mi][0], af[mi][1], af[mi][2],
                             af[mi][3], bf[ni][0], bf[ni][1]);
        }
        __syncthreads();
    }

    // epilogue: BN + ReLU6 -> NHWC fp16
#pragma unroll
    for (int mi = 0; mi < 4; mi++) {
#pragma unroll
        for (int h = 0; h < 2; h++) {
            int m = wm + mi * 16 + (lane >> 2) + h * 8;
            int pp = pbase + m;
            int yp = pp / 114, xp = pp - yp * 114;
            if (yp >= 1 && yp <= 112 && xp >= 1 && xp <= 112) {
                __half* dst = g_h2 +
                    ((size_t)img * 12544 + (size_t)(yp - 1) * 112 + (xp - 1)) * 192;
#pragma unroll
                for (int ni = 0; ni < 3; ni++) {
                    int cch = wn + ni * 8 + 2 * (lane & 3);
                    float y0 = fmaf(acc[mi][ni][h * 2 + 0], bnS[cch], bnS[192 + cch]);
                    float y1 = fmaf(acc[mi][ni][h * 2 + 1], bnS[cch + 1], bnS[192 + cch + 1]);
                    y0 = fminf(fmaxf(y0, 0.0f), 6.0f);
                    y1 = fminf(fmaxf(y1, 0.0f), 6.0f);
                    uint32_t pk = (uint32_t)__half_as_ushort(__float2half_rn(y0)) |
                                  ((uint32_t)__half_as_ushort(__float2half_rn(y1)) << 16);
                    *(uint32_t*)(dst + cch) = pk;
                }
            }
        }
    }
}

// ---------------- conv3: 1x1 192->32 HMMA GEMM + BN + residual -------------
// 128 thr / 4 warps, BM=128, BN=32, K=192 (3 chunks of 64).
// SMEM: bn 256B @0 | A @1024 (3x16KB) | B @50176 (3x4KB) | stg @62464 (16KB)
#define C3_A0 1024
#define C3_B0 50176
#define C3_ST 62464
#define C3_SMEM (62464 + 16384 + 1024)

__global__ __launch_bounds__(128, 1) void conv3_mma(
    const float* __restrict__ x,
    const float* __restrict__ g3, const float* __restrict__ b3,
    const float* __restrict__ m3, const float* __restrict__ v3,
    float* __restrict__ out)
{
    extern __shared__ char dsm[];
    uint32_t sb = (smem_u32(dsm) + 1023u) & ~1023u;
    char* sbase = dsm + (sb - smem_u32(dsm));
    float* bnS = (float*)sbase;
    float* stg = (float*)(sbase + C3_ST);

    int tid = threadIdx.x, wid = tid >> 5, lane = tid & 31;
    int img  = blockIdx.y;
    int pix0 = blockIdx.x * 128;

    float alpha3 = g_alpha[2];
    if (tid < 32) {
        float is = rsqrtf(v3[tid] + EPS);
        bnS[tid]      = alpha3 * g3[tid] * is;
        bnS[32 + tid] = b3[tid] - m3[tid] * g3[tid] * is;
    }

    // B: [32 co x 192 ci] -> 3 SW128 chunks
    for (int i = tid; i < 768; i += 128) {
        int chv = i >> 8; int rem = i & 255;
        int row = rem >> 3, c16 = rem & 7;
        uint4 v = *(const uint4*)((const char*)(g_w3r + (size_t)row * 192 + chv * 64) + c16 * 16);
        *(uint4*)(sbase + C3_B0 + chv * 4096 + SWZ(row * 128 + c16 * 16)) = v;
    }
    // A: h2 [128 pix x 192 ci] -> 3 SW128 chunks
    const __half* h2i = g_h2 + ((size_t)img * 12544 + pix0) * 192;
#pragma unroll
    for (int chv = 0; chv < 3; chv++) {
        for (int i = tid; i < 1024; i += 128) {
            int row = i >> 3, c16 = i & 7;
            uint4 v = *(const uint4*)((const char*)(h2i + (size_t)row * 192 + chv * 64) + c16 * 16);
            *(uint4*)(sbase + C3_A0 + chv * 16384 + SWZ(row * 128 + c16 * 16)) = v;
        }
    }
    __syncthreads();

    int wm = wid * 32;
    float acc[2][4][4];
#pragma unroll
    for (int a = 0; a < 2; a++)
#pragma unroll
        for (int b = 0; b < 4; b++)
#pragma unroll
            for (int c = 0; c < 4; c++) acc[a][b][c] = 0.0f;

#pragma unroll
    for (int chv = 0; chv < 3; chv++) {
        uint32_t sA = sb + C3_A0 + chv * 16384;
        uint32_t sB = sb + C3_B0 + chv * 4096;
#pragma unroll
        for (int kk = 0; kk < 4; kk++) {
            uint32_t bf[4][2];
#pragma unroll
            for (int ni = 0; ni < 4; ni++) {
                uint32_t a = sB + SWZ((ni * 8 + (lane & 7)) * 128 +
                                      (kk * 16 + ((lane >> 3) & 1) * 8) * 2);
                ldsm2(a, bf[ni][0], bf[ni][1]);
            }
#pragma unroll
            for (int mi = 0; mi < 2; mi++) {
                int m_loc = wm + mi * 16 + (lane & 7) + ((lane >> 3) & 1) * 8;
                int kh = kk * 16 + (lane >> 4) * 8;
                uint32_t af0, af1, af2, af3;
                ldsm4(sA + SWZ(m_loc * 128 + kh * 2), af0, af1, af2, af3);
#pragma unroll
                for (int ni = 0; ni < 4; ni++)
                    mma16816(acc[mi][ni], af0, af1, af2, af3, bf[ni][0], bf[ni][1]);
            }
        }
    }

    // BN -> stage in smem (transpose to channel-major)
#pragma unroll
    for (int mi = 0; mi < 2; mi++)
#pragma unroll
        for (int h = 0; h < 2; h++) {
            int m = wm + mi * 16 + (lane >> 2) + h * 8;
#pragma unroll
            for (int ni = 0; ni < 4; ni++) {
                int c = ni * 8 + 2 * (lane & 3);
                stg[c * 128 + m]       = fmaf(acc[mi][ni][h * 2 + 0], bnS[c],     bnS[32 + c]);
                stg[(c + 1) * 128 + m] = fmaf(acc[mi][ni][h * 2 + 1], bnS[c + 1], bnS[32 + c + 1]);
            }
        }
    __syncthreads();

    // coalesced NCHW store with residual
    for (int c = 0; c < 32; c++) {
        size_t o = ((size_t)img * 32 + c) * HW + pix0 + tid;
        out[o] = stg[c * 128 + tid] + x[o];
    }
}

// ---------------- launch ----------------------------------------------------
extern "C" void kernel_launch(void* const* d_in, const int* in_sizes, int n_in,
                              void* d_out, int out_size) {
    const float* x  = (const float*)d_in[0];
    const float* w1 = (const float*)d_in[1];
    const float* g1 = (const float*)d_in[2];
    const float* b1 = (const float*)d_in[3];
    const float* m1 = (const float*)d_in[4];
    const float* v1 = (const float*)d_in[5];
    const float* w2 = (const float*)d_in[6];
    const float* g2 = (const float*)d_in[7];
    const float* b2 = (const float*)d_in[8];
    const float* m2 = (const float*)d_in[9];
    const float* v2 = (const float*)d_in[10];
    const float* w3 = (const float*)d_in[11];
    const float* g3 = (const float*)d_in[12];
    const float* b3 = (const float*)d_in[13];
    const float* m3 = (const float*)d_in[14];
    const float* v3 = (const float*)d_in[15];
    float* out = (float*)d_out;

    cudaFuncSetAttribute(conv2_mma, cudaFuncAttributeMaxDynamicSharedMemorySize, C2_SMEM);
    cudaFuncSetAttribute(conv3_mma, cudaFuncAttributeMaxDynamicSharedMemorySize, C3_SMEM);

    // TWN stats (deterministic 2-stage)
    stats_abs_part<<<4, 256>>>(w1, 6144);
    stats_delta_fin<<<1, 256>>>(4, 6144, 0);
    stats_alpha_part<<<4, 256>>>(w1, 6144, 0);
    stats_alpha_fin<<<1, 256>>>(4, 0);

    stats_abs_part<<<148, 256>>>(w2, 331776);
    stats_delta_fin<<<1, 256>>>(148, 331776, 1);
    stats_alpha_part<<<148, 256>>>(w2, 331776, 1);
    stats_alpha_fin<<<1, 256>>>(148, 1);

    stats_abs_part<<<4, 256>>>(w3, 6144);
    stats_delta_fin<<<1, 256>>>(4, 6144, 2);
    stats_alpha_part<<<4, 256>>>(w3, 6144, 2);
    stats_alpha_fin<<<1, 256>>>(4, 2);

    prep_w1<<<24, 256>>>(w1);
    prep_w2<<<324, 256>>>(w2);
    prep_w3<<<24, 256>>>(w3);

    conv1_kernel<<<dim3(49, 6, 16), 256>>>(x, g1, b1, m1, v1);
    conv2_mma<<<dim3(100, 16), 512, C2_SMEM>>>(g2, b2, m2, v2);
    conv3_mma<<<dim3(98, 16), 128, C3_SMEM>>>(x, g3, b3, m3, v3, out);
}

// round 5
// speedup vs baseline: 8.6827x; 1.4009x over previous
#include <cuda_runtime.h>
#include <cuda_fp16.h>
#include <math.h>
#include <stdint.h>

#define EPS 1e-5f
static const int HW = 112 * 112;      // 12544
static const int PPIX = 13184;        // padded pixels per image (114*114=12996 -> 13184)

// ---------------- scratch (device globals; zero-initialized) ---------------
__device__ __half g_w1r[192 * 32];                  // ±1 fp16 [co][ci]
__device__ __half g_w2r[9 * 192 * 192];             // ±1 fp16 [shift][co][ci]
__device__ __half g_w3r[32 * 192];                  // ±1 fp16 [co][ci]
__device__ __half g_h1p[(size_t)16 * PPIX * 192];   // padded NHWC fp16 (~81MB)
__device__ float  g_delta[3];
__device__ float  g_alpha[3];
__device__ double g_partd[3][160];
__device__ int    g_parti[3][160];

// ---------------- helpers ----------------------------------------------------
__device__ __forceinline__ uint32_t smem_u32(const void* p) {
    uint32_t a;
    asm("{ .reg .u64 t; cvta.to.shared.u64 t, %1; cvt.u32.u64 %0, t; }"
        : "=r"(a) : "l"(p));
    return a;
}
#define SWZ(o) ((o) ^ (((o) >> 3) & 0x70))

#define CP_ASYNC16(saddr, gaddr) \
    asm volatile("cp.async.cg.shared.global [%0], [%1], 16;" \
        :: "r"(saddr), "l"(gaddr) : "memory")
#define CP_COMMIT() asm volatile("cp.async.commit_group;" ::: "memory")
#define CP_WAIT1()  asm volatile("cp.async.wait_group 1;" ::: "memory")
#define CP_WAIT0()  asm volatile("cp.async.wait_group 0;" ::: "memory")

__device__ __forceinline__ void ldsm4(uint32_t a, uint32_t& r0, uint32_t& r1,
                                      uint32_t& r2, uint32_t& r3) {
    asm volatile("ldmatrix.sync.aligned.m8n8.x4.shared.b16 {%0,%1,%2,%3}, [%4];"
        : "=r"(r0), "=r"(r1), "=r"(r2), "=r"(r3) : "r"(a));
}
__device__ __forceinline__ void ldsm2(uint32_t a, uint32_t& r0, uint32_t& r1) {
    asm volatile("ldmatrix.sync.aligned.m8n8.x2.shared.b16 {%0,%1}, [%2];"
        : "=r"(r0), "=r"(r1) : "r"(a));
}
__device__ __forceinline__ void mma16816(float* c, uint32_t a0, uint32_t a1,
                                         uint32_t a2, uint32_t a3,
                                         uint32_t b0, uint32_t b1) {
    asm volatile(
        "mma.sync.aligned.m16n8k16.row.col.f32.f16.f16.f32 "
        "{%0,%1,%2,%3}, {%4,%5,%6,%7}, {%8,%9}, {%0,%1,%2,%3};"
        : "+f"(c[0]), "+f"(c[1]), "+f"(c[2]), "+f"(c[3])
        : "r"(a0), "r"(a1), "r"(a2), "r"(a3), "r"(b0), "r"(b1));
}

// ---------------- TWN stats: batched 2-stage deterministic reduction -------
__global__ void stats_abs_all(const float* __restrict__ w1,
                              const float* __restrict__ w2,
                              const float* __restrict__ w3) {
    __shared__ double sd[256];
    int slot = blockIdx.y;
    const float* w = (slot == 0) ? w1 : (slot == 1) ? w2 : w3;
    int n = (slot == 1) ? 331776 : 6144;
    int tid = threadIdx.x;
    int g = blockIdx.x * 256 + tid, stride = gridDim.x * 256;
    double s = 0.0;
    for (int i = g; i < n; i += stride) s += (double)fabsf(w[i]);
    sd[tid] = s; __syncthreads();
    for (int o = 128; o > 0; o >>= 1) {
        if (tid < o) sd[tid] += sd[tid + o];
        __syncthreads();
    }
    if (tid == 0) g_partd[slot][blockIdx.x] = sd[0];
}
__global__ void stats_delta_all() {
    __shared__ double sd[256];
    int slot = blockIdx.x;
    int n = (slot == 1) ? 331776 : 6144;
    int tid = threadIdx.x;
    sd[tid] = (tid < 148) ? g_partd[slot][tid] : 0.0; __syncthreads();
    for (int o = 128; o > 0; o >>= 1) {
        if (tid < o) sd[tid] += sd[tid + o];
        __syncthreads();
    }
    if (tid == 0) g_delta[slot] = (float)(0.7 * sd[0] / (double)n);
}
__global__ void stats_alpha_all(const float* __restrict__ w1,
                                const float* __restrict__ w2,
                                const float* __restrict__ w3) {
    __shared__ double sd[256];
    __shared__ int    si[256];
    int slot = blockIdx.y;
    const float* w = (slot == 0) ? w1 : (slot == 1) ? w2 : w3;
    int n = (slot == 1) ? 331776 : 6144;
    int tid = threadIdx.x;
    int g = blockIdx.x * 256 + tid, stride = gridDim.x * 256;
    float delta = g_delta[slot];
    double s = 0.0; int c = 0;
    for (int i = g; i < n; i += stride) {
        float a = fabsf(w[i]);
        if (a > delta) { s += (double)a; c++; }
    }
    sd[tid] = s; si[tid] = c; __syncthreads();
    for (int o = 128; o > 0; o >>= 1) {
        if (tid < o) { sd[tid] += sd[tid + o]; si[tid] += si[tid + o]; }
        __syncthreads();
    }
    if (tid == 0) { g_partd[slot][blockIdx.x] = sd[0]; g_parti[slot][blockIdx.x] = si[0]; }
}
__global__ void stats_alpha_fin_all() {
    __shared__ double sd[256];
    __shared__ int    si[256];
    int slot = blockIdx.x;
    int tid = threadIdx.x;
    sd[tid] = (tid < 148) ? g_partd[slot][tid] : 0.0;
    si[tid] = (tid < 148) ? g_parti[slot][tid] : 0;
    __syncthreads();
    for (int o = 128; o > 0; o >>= 1) {
        if (tid < o) { sd[tid] += sd[tid + o]; si[tid] += si[tid + o]; }
        __syncthreads();
    }
    if (tid == 0) {
        int cnt = si[0] < 1 ? 1 : si[0];
        g_alpha[slot] = (float)(sd[0] / (double)cnt);
    }
}

// prep: blocks 0..323 -> w2 rearrange; 324 -> w1; 325 -> w3 (all ±1 fp16)
__global__ void prep_all(const float* __restrict__ w1,
                         const float* __restrict__ w2,
                         const float* __restrict__ w3) {
    int bid = blockIdx.x, tid = threadIdx.x;
    if (bid < 324) {
        float delta = g_delta[1];
        int base = bid * 1024;
#pragma unroll
        for (int it = 0; it < 4; it++) {
            int i = base + it * 256 + tid;
            int co = i / 1728; int rem = i - co * 1728;
            int ci = rem / 9;  int kk = rem - ci * 9;
            float wv = w2[i];
            float q = (fabsf(wv) > delta) ? (wv > 0.0f ? 1.0f : -1.0f) : 0.0f;
            g_w2r[((size_t)kk * 192 + co) * 192 + ci] = __float2half_rn(q);
        }
    } else if (bid == 324) {
        float delta = g_delta[0];
        for (int i = tid; i < 6144; i += 256) {
            float wv = w1[i];
            float q = (fabsf(wv) > delta) ? (wv > 0.0f ? 1.0f : -1.0f) : 0.0f;
            g_w1r[i] = __float2half_rn(q);
        }
    } else {
        float delta = g_delta[2];
        for (int i = tid; i < 6144; i += 256) {
            float wv = w3[i];
            float q = (fabsf(wv) > delta) ? (wv > 0.0f ? 1.0f : -1.0f) : 0.0f;
            g_w3r[i] = __float2half_rn(q);
        }
    }
}

// ---------------- conv1: 1x1 32->192 HMMA, BN + ReLU6 -> padded NHWC fp16 --
// grid (98, 16), 256 thr / 8 warps (2M x 4N), BM=128, BN=192, K=32.
#define C1_BN  0
#define C1_A   2048
#define C1_B   (2048 + 16384)
#define C1_SMEM (2048 + 16384 + 24576 + 1024)

__global__ __launch_bounds__(256) void conv1_mma(
    const float* __restrict__ x,
    const float* __restrict__ g1, const float* __restrict__ b1,
    const float* __restrict__ m1, const float* __restrict__ v1)
{
    extern __shared__ char dsm[];
    uint32_t sb = (smem_u32(dsm) + 1023u) & ~1023u;
    char* sbase = dsm + (sb - smem_u32(dsm));
    float* bnS = (float*)(sbase + C1_BN);

    int tid = threadIdx.x, wid = tid >> 5, lane = tid & 31;
    int img  = blockIdx.y;
    int pix0 = blockIdx.x * 128;

    // B (w1r) via cp.async: 192 rows x 64B (first half of 128B SW128 rows)
    for (int i = tid; i < 768; i += 256) {
        int row = i >> 2, c16 = i & 3;
        CP_ASYNC16(sb + C1_B + SWZ(row * 128 + c16 * 16),
                   (const char*)(g_w1r + row * 32) + c16 * 16);
    }
    CP_COMMIT();

    float alpha1 = g_alpha[0];
    for (int c = tid; c < 192; c += 256) {
        float is = rsqrtf(v1[c] + EPS);
        bnS[c]       = alpha1 * g1[c] * is;
        bnS[192 + c] = b1[c] - m1[c] * g1[c] * is;
    }

    // A: x fp32 NCHW -> fp16 [pix][ci] SW128
    {
        int p = tid & 127, cg = tid >> 7;  // 2 ci-groups of 16
        const float* xb = x + (size_t)img * 32 * HW + pix0 + p;
#pragma unroll
        for (int i = 0; i < 8; i++) {
            int ci = cg * 16 + i * 2;
            float f0 = xb[(size_t)ci * HW];
            float f1 = xb[(size_t)(ci + 1) * HW];
            uint32_t pk = (uint32_t)__half_as_ushort(__float2half_rn(f0)) |
                          ((uint32_t)__half_as_ushort(__float2half_rn(f1)) << 16);
            *(uint32_t*)(sbase + C1_A + SWZ(p * 128 + ci * 2)) = pk;
        }
    }
    CP_WAIT0();
    __syncthreads();

    int wm = (wid >> 2) * 64;
    int wn = (wid & 3) * 48;
    float acc[4][6][4];
#pragma unroll
    for (int a = 0; a < 4; a++)
#pragma unroll
        for (int b = 0; b < 6; b++)
#pragma unroll
            for (int c = 0; c < 4; c++) acc[a][b][c] = 0.0f;

#pragma unroll
    for (int kk = 0; kk < 2; kk++) {
        uint32_t bf[6][2];
#pragma unroll
        for (int bb = 0; bb < 3; bb++) {
            int r = wn + bb * 16 + ((lane >> 4) & 1) * 8 + (lane & 7);
            int kcol = kk * 16 + ((lane >> 3) & 1) * 8;
            uint32_t q0, q1, q2, q3;
            ldsm4(sb + C1_B + SWZ(r * 128 + kcol * 2), q0, q1, q2, q3);
            bf[2 * bb][0] = q0; bf[2 * bb][1] = q1;
            bf[2 * bb + 1][0] = q2; bf[2 * bb + 1][1] = q3;
        }
#pragma unroll
        for (int mi = 0; mi < 4; mi++) {
            int m_loc = wm + mi * 16 + (lane & 7) + ((lane >> 3) & 1) * 8;
            int kh = kk * 16 + (lane >> 4) * 8;
            uint32_t a0, a1, a2, a3;
            ldsm4(sb + C1_A + SWZ(m_loc * 128 + kh * 2), a0, a1, a2, a3);
#pragma unroll
            for (int ni = 0; ni < 6; ni++)
                mma16816(acc[mi][ni], a0, a1, a2, a3, bf[ni][0], bf[ni][1]);
        }
    }

    // epilogue: BN1 + ReLU6 -> padded NHWC fp16 (u32 scatter)
    __half* h1b = g_h1p + (size_t)img * PPIX * 192;
#pragma unroll
    for (int mi = 0; mi < 4; mi++) {
#pragma unroll
        for (int h = 0; h < 2; h++) {
            int m = wm + mi * 16 + (lane >> 2) + h * 8;
            int pu = pix0 + m;
            int y = pu / 112, xx = pu - y * 112;
            __half* dst = h1b + (size_t)((y + 1) * 114 + xx + 1) * 192;
#pragma unroll
            for (int ni = 0; ni < 6; ni++) {
                int c = wn + ni * 8 + 2 * (lane & 3);
                float y0 = fmaf(acc[mi][ni][h * 2 + 0], bnS[c],     bnS[192 + c]);
                float y1 = fmaf(acc[mi][ni][h * 2 + 1], bnS[c + 1], bnS[192 + c + 1]);
                y0 = fminf(fmaxf(y0, 0.0f), 6.0f);
                y1 = fminf(fmaxf(y1, 0.0f), 6.0f);
                uint32_t pk = (uint32_t)__half_as_ushort(__float2half_rn(y0)) |
                              ((uint32_t)__half_as_ushort(__float2half_rn(y1)) << 16);
                *(uint32_t*)(dst + c) = pk;
            }
        }
    }
}

// ---------------- conv2 (3x3) + conv3 (1x1) fused ---------------------------
// grid (67, 16), 384 thr / 12 warps. BM=192 padded pixels, BN=192,
// K = 9 shifts x 3 chunks of 64. Warp grid 3(M) x 4(N), tile 64x48.
// After mainloop: BN2+ReLU6 -> SMEM h2 tile, then conv3 GEMM (K=192, N=32),
// BN3 + residual, masked NCHW store. g_h2 eliminated.
#define F_BN2  0          // 1536
#define F_BN3  1536       // 256
#define F_W3   2048       // 12288
#define F_A0   14336      // 24576
#define F_A1   38912      // 24576
#define F_B0   63488      // 24576
#define F_B1   88064      // 24576
#define F_H2S  14336      // 73728 (overlays A0,A1,B0 after mainloop)
#define F_SMEM (112640 + 1024)

__global__ __launch_bounds__(384, 1) void conv23_fused(
    const float* __restrict__ g2, const float* __restrict__ b2,
    const float* __restrict__ m2, const float* __restrict__ v2,
    const float* __restrict__ g3, const float* __restrict__ b3,
    const float* __restrict__ m3, const float* __restrict__ v3,
    const float* __restrict__ x, float* __restrict__ out)
{
    extern __shared__ char dsm[];
    uint32_t sb = (smem_u32(dsm) + 1023u) & ~1023u;
    char* sbase = dsm + (sb - smem_u32(dsm));
    float* bn2 = (float*)(sbase + F_BN2);
    float* bn3 = (float*)(sbase + F_BN3);

    int tid = threadIdx.x, wid = tid >> 5, lane = tid & 31;
    int img   = blockIdx.y;
    int pbase = 115 + blockIdx.x * 192;

    // w3 -> SMEM (3 SW128 chunks of [32co x 64ci])
    for (int i = tid; i < 768; i += 384) {
        int ch = i >> 8; int rem = i & 255;
        int row = rem >> 3, c16 = rem & 7;
        CP_ASYNC16(sb + F_W3 + ch * 4096 + SWZ(row * 128 + c16 * 16),
                   (const char*)(g_w3r + row * 192 + ch * 64) + c16 * 16);
    }

    float alpha2 = g_alpha[1], alpha3 = g_alpha[2];
    for (int c = tid; c < 192; c += 384) {
        float is = rsqrtf(v2[c] + EPS);
        bn2[c]       = alpha2 * g2[c] * is;
        bn2[192 + c] = b2[c] - m2[c] * g2[c] * is;
    }
    if (tid < 32) {
        float is = rsqrtf(v3[tid] + EPS);
        bn3[tid]      = alpha3 * g3[tid] * is;
        bn3[32 + tid] = b3[tid] - m3[tid] * g3[tid] * is;
    }

    const __half* h1i = g_h1p + (size_t)img * PPIX * 192;

    auto load_chunk = [&](int chunk) {
        int sh = chunk / 3, ch = chunk - sh * 3;
        int soff = (sh / 3 - 1) * 114 + (sh % 3 - 1);
        const __half* ain = h1i + (size_t)(pbase + soff) * 192 + ch * 64;
        const __half* bw  = g_w2r + (size_t)sh * 36864 + (size_t)ch * 64;
        uint32_t sA = sb + F_A0 + (chunk & 1) * 24576;
        uint32_t sB = sb + F_B0 + (chunk & 1) * 24576;
#pragma unroll
        for (int p = 0; p < 4; p++) {
            int lin = p * 384 + tid;
            int row = lin >> 3, c16 = lin & 7;
            CP_ASYNC16(sA + SWZ(row * 128 + c16 * 16),
                       (const char*)(ain + (size_t)row * 192) + c16 * 16);
        }
#pragma unroll
        for (int p = 0; p < 4; p++) {
            int lin = p * 384 + tid;
            int row = lin >> 3, c16 = lin & 7;
            CP_ASYNC16(sB + SWZ(row * 128 + c16 * 16),
                       (const char*)(bw + (size_t)row * 192) + c16 * 16);
        }
    };

    int wm = (wid >> 2) * 64;     // 0,64,128
    int wn = (wid & 3) * 48;      // 0..144

    float acc[4][6][4];
#pragma unroll
    for (int a = 0; a < 4; a++)
#pragma unroll
        for (int b = 0; b < 6; b++)
#pragma unroll
            for (int c = 0; c < 4; c++) acc[a][b][c] = 0.0f;

    load_chunk(0);
    CP_COMMIT();

    for (int c = 0; c < 27; c++) {
        if (c + 1 < 27) load_chunk(c + 1);
        CP_COMMIT();
        CP_WAIT1();
        __syncthreads();

        uint32_t sA = sb + F_A0 + (c & 1) * 24576;
        uint32_t sB = sb + F_B0 + (c & 1) * 24576;
#pragma unroll
        for (int kk = 0; kk < 4; kk++) {
            uint32_t bf[6][2];
#pragma unroll
            for (int bb = 0; bb < 3; bb++) {
                int r = wn + bb * 16 + ((lane >> 4) & 1) * 8 + (lane & 7);
                int kcol = kk * 16 + ((lane >> 3) & 1) * 8;
                uint32_t q0, q1, q2, q3;
                ldsm4(sB + SWZ(r * 128 + kcol * 2), q0, q1, q2, q3);
                bf[2 * bb][0] = q0; bf[2 * bb][1] = q1;
                bf[2 * bb + 1][0] = q2; bf[2 * bb + 1][1] = q3;
            }
#pragma unroll
            for (int mi = 0; mi < 4; mi++) {
                int m_loc = wm + mi * 16 + (lane & 7) + ((lane >> 3) & 1) * 8;
                int kh = kk * 16 + (lane >> 4) * 8;
                uint32_t a0, a1, a2, a3;
                ldsm4(sA + SWZ(m_loc * 128 + kh * 2), a0, a1, a2, a3);
#pragma unroll
                for (int ni = 0; ni < 6; ni++)
                    mma16816(acc[mi][ni], a0, a1, a2, a3, bf[ni][0], bf[ni][1]);
            }
        }
        __syncthreads();
    }

    // ---- BN2 + ReLU6 -> SMEM h2 tile (fp16, 3 SW128 chunks of 64 ci) ----
    char* h2s = sbase + F_H2S;
#pragma unroll
    for (int mi = 0; mi < 4; mi++) {
#pragma unroll
        for (int h = 0; h < 2; h++) {
            int m = wm + mi * 16 + (lane >> 2) + h * 8;
#pragma unroll
            for (int ni = 0; ni < 6; ni++) {
                int cch = wn + ni * 8 + 2 * (lane & 3);
                float y0 = fmaf(acc[mi][ni][h * 2 + 0], bn2[cch],     bn2[192 + cch]);
                float y1 = fmaf(acc[mi][ni][h * 2 + 1], bn2[cch + 1], bn2[192 + cch + 1]);
                y0 = fminf(fmaxf(y0, 0.0f), 6.0f);
                y1 = fminf(fmaxf(y1, 0.0f), 6.0f);
                uint32_t pk = (uint32_t)__half_as_ushort(__float2half_rn(y0)) |
                              ((uint32_t)__half_as_ushort(__float2half_rn(y1)) << 16);
                *(uint32_t*)(h2s + (cch >> 6) * 24576 + SWZ(m * 128 + (cch & 63) * 2)) = pk;
            }
        }
    }
    __syncthreads();

    // ---- conv3: M=192, N=32, K=192 from SMEM ----
    int wm3 = (wid >> 2) * 64;
    int wn3 = (wid & 3) * 8;
    float acc3[4][4];
#pragma unroll
    for (int a = 0; a < 4; a++)
#pragma unroll
        for (int c = 0; c < 4; c++) acc3[a][c] = 0.0f;

#pragma unroll
    for (int ch = 0; ch < 3; ch++) {
        uint32_t sA = sb + F_H2S + ch * 24576;
        uint32_t sB = sb + F_W3 + ch * 4096;
#pragma unroll
        for (int kk = 0; kk < 4; kk++) {
            uint32_t b0, b1;
            ldsm2(sB + SWZ((wn3 + (lane & 7)) * 128 +
                           (kk * 16 + ((lane >> 3) & 1) * 8) * 2), b0, b1);
#pragma unroll
            for (int mi = 0; mi < 4; mi++) {
                int m_loc = wm3 + mi * 16 + (lane & 7) + ((lane >> 3) & 1) * 8;
                int kh = kk * 16 + (lane >> 4) * 8;
                uint32_t a0, a1, a2, a3;
                ldsm4(sA + SWZ(m_loc * 128 + kh * 2), a0, a1, a2, a3);
                mma16816(acc3[mi], a0, a1, a2, a3, b0, b1);
            }
        }
    }

    // ---- BN3 + residual + masked NCHW store ----
    const float* xi = x + (size_t)img * 32 * HW;
    float* oi = out + (size_t)img * 32 * HW;
#pragma unroll
    for (int mi = 0; mi < 4; mi++) {
#pragma unroll
        for (int h = 0; h < 2; h++) {
            int m = wm3 + mi * 16 + (lane >> 2) + h * 8;
            int pp = pbase + m;
            int yp = pp / 114, xq = pp - yp * 114;
            if (yp >= 1 && yp <= 112 && xq >= 1 && xq <= 112) {
                int up = (yp - 1) * 112 + (xq - 1);
                int c = wn3 + 2 * (lane & 3);
                size_t i0 = (size_t)c * HW + up;
                size_t i1 = i0 + HW;
                oi[i0] = fmaf(acc3[mi][h * 2 + 0], bn3[c],     bn3[32 + c])     + xi[i0];
                oi[i1] = fmaf(acc3[mi][h * 2 + 1], bn3[c + 1], bn3[32 + c + 1]) + xi[i1];
            }
        }
    }
}

// ---------------- launch ----------------------------------------------------
extern "C" void kernel_launch(void* const* d_in, const int* in_sizes, int n_in,
                              void* d_out, int out_size) {
    const float* x  = (const float*)d_in[0];
    const float* w1 = (const float*)d_in[1];
    const float* g1 = (const float*)d_in[2];
    const float* b1 = (const float*)d_in[3];
    const float* m1 = (const float*)d_in[4];
    const float* v1 = (const float*)d_in[5];
    const float* w2 = (const float*)d_in[6];
    const float* g2 = (const float*)d_in[7];
    const float* b2 = (const float*)d_in[8];
    const float* m2 = (const float*)d_in[9];
    const float* v2 = (const float*)d_in[10];
    const float* w3 = (const float*)d_in[11];
    const float* g3 = (const float*)d_in[12];
    const float* b3 = (const float*)d_in[13];
    const float* m3 = (const float*)d_in[14];
    const float* v3 = (const float*)d_in[15];
    float* out = (float*)d_out;

    cudaFuncSetAttribute(conv1_mma, cudaFuncAttributeMaxDynamicSharedMemorySize, C1_SMEM);
    cudaFuncSetAttribute(conv23_fused, cudaFuncAttributeMaxDynamicSharedMemorySize, F_SMEM);

    stats_abs_all<<<dim3(148, 3), 256>>>(w1, w2, w3);
    stats_delta_all<<<3, 256>>>();
    stats_alpha_all<<<dim3(148, 3), 256>>>(w1, w2, w3);
    stats_alpha_fin_all<<<3, 256>>>();
    prep_all<<<326, 256>>>(w1, w2, w3);

    conv1_mma<<<dim3(98, 16), 256, C1_SMEM>>>(x, g1, b1, m1, v1);
    conv23_fused<<<dim3(67, 16), 384, F_SMEM>>>(g2, b2, m2, v2,
                                                g3, b3, m3, v3, x, out);
}

// round 6
// speedup vs baseline: 8.7845x; 1.0117x over previous
#include <cuda_runtime.h>
#include <cuda_fp16.h>
#include <math.h>
#include <stdint.h>

#define EPS 1e-5f
static const int HW = 112 * 112;      // 12544
static const int PPIX = 13184;        // padded pixels per image (114*114=12996 -> 13184)

// ---------------- scratch (device globals; zero-initialized) ---------------
__device__ __half g_w1r[192 * 32];                  // ±1 fp16 [co][ci]
__device__ __half g_w2r[9 * 192 * 192];             // ±1 fp16 [shift][co][ci]
__device__ __half g_w3r[32 * 192];                  // ±1 fp16 [co][ci]
__device__ __half g_h1p[(size_t)16 * PPIX * 192];   // padded NHWC fp16 (~81MB)
__device__ float  g_delta[3];
__device__ float  g_alpha[3];
__device__ double g_partd[3][160];
__device__ int    g_parti[3][160];

// ---------------- helpers ----------------------------------------------------
__device__ __forceinline__ uint32_t smem_u32(const void* p) {
    uint32_t a;
    asm("{ .reg .u64 t; cvta.to.shared.u64 t, %1; cvt.u32.u64 %0, t; }"
        : "=r"(a) : "l"(p));
    return a;
}
#define SWZ(o) ((o) ^ (((o) >> 3) & 0x70))

#define CP_ASYNC16(saddr, gaddr) \
    asm volatile("cp.async.cg.shared.global [%0], [%1], 16;" \
        :: "r"(saddr), "l"(gaddr) : "memory")
#define CP_COMMIT() asm volatile("cp.async.commit_group;" ::: "memory")
#define CP_WAIT1()  asm volatile("cp.async.wait_group 1;" ::: "memory")
#define CP_WAIT0()  asm volatile("cp.async.wait_group 0;" ::: "memory")

__device__ __forceinline__ void ldsm4(uint32_t a, uint32_t& r0, uint32_t& r1,
                                      uint32_t& r2, uint32_t& r3) {
    asm volatile("ldmatrix.sync.aligned.m8n8.x4.shared.b16 {%0,%1,%2,%3}, [%4];"
        : "=r"(r0), "=r"(r1), "=r"(r2), "=r"(r3) : "r"(a));
}
__device__ __forceinline__ void ldsm2(uint32_t a, uint32_t& r0, uint32_t& r1) {
    asm volatile("ldmatrix.sync.aligned.m8n8.x2.shared.b16 {%0,%1}, [%2];"
        : "=r"(r0), "=r"(r1) : "r"(a));
}
__device__ __forceinline__ void mma16816(float* c, uint32_t a0, uint32_t a1,
                                         uint32_t a2, uint32_t a3,
                                         uint32_t b0, uint32_t b1) {
    asm volatile(
        "mma.sync.aligned.m16n8k16.row.col.f32.f16.f16.f32 "
        "{%0,%1,%2,%3}, {%4,%5,%6,%7}, {%8,%9}, {%0,%1,%2,%3};"
        : "+f"(c[0]), "+f"(c[1]), "+f"(c[2]), "+f"(c[3])
        : "r"(a0), "r"(a1), "r"(a2), "r"(a3), "r"(b0), "r"(b1));
}

// ---------------- TWN stats: batched 2-stage deterministic reduction -------
__global__ void stats_abs_all(const float* __restrict__ w1,
                              const float* __restrict__ w2,
                              const float* __restrict__ w3) {
    __shared__ double sd[256];
    int slot = blockIdx.y;
    const float* w = (slot == 0) ? w1 : (slot == 1) ? w2 : w3;
    int n = (slot == 1) ? 331776 : 6144;
    int tid = threadIdx.x;
    int g = blockIdx.x * 256 + tid, stride = gridDim.x * 256;
    double s = 0.0;
    for (int i = g; i < n; i += stride) s += (double)fabsf(w[i]);
    sd[tid] = s; __syncthreads();
    for (int o = 128; o > 0; o >>= 1) {
        if (tid < o) sd[tid] += sd[tid + o];
        __syncthreads();
    }
    if (tid == 0) g_partd[slot][blockIdx.x] = sd[0];
}
__global__ void stats_delta_all() {
    __shared__ double sd[256];
    int slot = blockIdx.x;
    int n = (slot == 1) ? 331776 : 6144;
    int tid = threadIdx.x;
    sd[tid] = (tid < 148) ? g_partd[slot][tid] : 0.0; __syncthreads();
    for (int o = 128; o > 0; o >>= 1) {
        if (tid < o) sd[tid] += sd[tid + o];
        __syncthreads();
    }
    if (tid == 0) g_delta[slot] = (float)(0.7 * sd[0] / (double)n);
}
__global__ void stats_alpha_all(const float* __restrict__ w1,
                                const float* __restrict__ w2,
                                const float* __restrict__ w3) {
    __shared__ double sd[256];
    __shared__ int    si[256];
    int slot = blockIdx.y;
    const float* w = (slot == 0) ? w1 : (slot == 1) ? w2 : w3;
    int n = (slot == 1) ? 331776 : 6144;
    int tid = threadIdx.x;
    int g = blockIdx.x * 256 + tid, stride = gridDim.x * 256;
    float delta = g_delta[slot];
    double s = 0.0; int c = 0;
    for (int i = g; i < n; i += stride) {
        float a = fabsf(w[i]);
        if (a > delta) { s += (double)a; c++; }
    }
    sd[tid] = s; si[tid] = c; __syncthreads();
    for (int o = 128; o > 0; o >>= 1) {
        if (tid < o) { sd[tid] += sd[tid + o]; si[tid] += si[tid + o]; }
        __syncthreads();
    }
    if (tid == 0) { g_partd[slot][blockIdx.x] = sd[0]; g_parti[slot][blockIdx.x] = si[0]; }
}
__global__ void stats_alpha_fin_all() {
    __shared__ double sd[256];
    __shared__ int    si[256];
    int slot = blockIdx.x;
    int tid = threadIdx.x;
    sd[tid] = (tid < 148) ? g_partd[slot][tid] : 0.0;
    si[tid] = (tid < 148) ? g_parti[slot][tid] : 0;
    __syncthreads();
    for (int o = 128; o > 0; o >>= 1) {
        if (tid < o) { sd[tid] += sd[tid + o]; si[tid] += si[tid + o]; }
        __syncthreads();
    }
    if (tid == 0) {
        int cnt = si[0] < 1 ? 1 : si[0];
        g_alpha[slot] = (float)(sd[0] / (double)cnt);
    }
}

// prep: blocks 0..323 -> w2 rearrange; 324 -> w1; 325 -> w3 (all ±1 fp16)
__global__ void prep_all(const float* __restrict__ w1,
                         const float* __restrict__ w2,
                         const float* __restrict__ w3) {
    int bid = blockIdx.x, tid = threadIdx.x;
    if (bid < 324) {
        float delta = g_delta[1];
        int base = bid * 1024;
#pragma unroll
        for (int it = 0; it < 4; it++) {
            int i = base + it * 256 + tid;
            int co = i / 1728; int rem = i - co * 1728;
            int ci = rem / 9;  int kk = rem - ci * 9;
            float wv = w2[i];
            float q = (fabsf(wv) > delta) ? (wv > 0.0f ? 1.0f : -1.0f) : 0.0f;
            g_w2r[((size_t)kk * 192 + co) * 192 + ci] = __float2half_rn(q);
        }
    } else if (bid == 324) {
        float delta = g_delta[0];
        for (int i = tid; i < 6144; i += 256) {
            float wv = w1[i];
            float q = (fabsf(wv) > delta) ? (wv > 0.0f ? 1.0f : -1.0f) : 0.0f;
            g_w1r[i] = __float2half_rn(q);
        }
    } else {
        float delta = g_delta[2];
        for (int i = tid; i < 6144; i += 256) {
            float wv = w3[i];
            float q = (fabsf(wv) > delta) ? (wv > 0.0f ? 1.0f : -1.0f) : 0.0f;
            g_w3r[i] = __float2half_rn(q);
        }
    }
}

// ---------------- conv1: 1x1 32->192 HMMA, BN + ReLU6 -> padded NHWC fp16 --
// grid (98, 16), 256 thr / 8 warps (2M x 4N), BM=128, BN=192, K=32.
#define C1_BN  0
#define C1_A   2048
#define C1_B   (2048 + 16384)
#define C1_SMEM (2048 + 16384 + 24576 + 1024)

__global__ __launch_bounds__(256) void conv1_mma(
    const float* __restrict__ x,
    const float* __restrict__ g1, const float* __restrict__ b1,
    const float* __restrict__ m1, const float* __restrict__ v1)
{
    extern __shared__ char dsm[];
    uint32_t sb = (smem_u32(dsm) + 1023u) & ~1023u;
    char* sbase = dsm + (sb - smem_u32(dsm));
    float* bnS = (float*)(sbase + C1_BN);

    int tid = threadIdx.x, wid = tid >> 5, lane = tid & 31;
    int img  = blockIdx.y;
    int pix0 = blockIdx.x * 128;

    // B (w1r) via cp.async: 192 rows x 64B (first half of 128B SW128 rows)
    for (int i = tid; i < 768; i += 256) {
        int row = i >> 2, c16 = i & 3;
        CP_ASYNC16(sb + C1_B + SWZ(row * 128 + c16 * 16),
                   (const char*)(g_w1r + row * 32) + c16 * 16);
    }
    CP_COMMIT();

    float alpha1 = g_alpha[0];
    for (int c = tid; c < 192; c += 256) {
        float is = rsqrtf(v1[c] + EPS);
        bnS[c]       = alpha1 * g1[c] * is;
        bnS[192 + c] = b1[c] - m1[c] * g1[c] * is;
    }

    // A: x fp32 NCHW -> fp16 [pix][ci] SW128
    {
        int p = tid & 127, cg = tid >> 7;  // 2 ci-groups of 16
        const float* xb = x + (size_t)img * 32 * HW + pix0 + p;
#pragma unroll
        for (int i = 0; i < 8; i++) {
            int ci = cg * 16 + i * 2;
            float f0 = xb[(size_t)ci * HW];
            float f1 = xb[(size_t)(ci + 1) * HW];
            uint32_t pk = (uint32_t)__half_as_ushort(__float2half_rn(f0)) |
                          ((uint32_t)__half_as_ushort(__float2half_rn(f1)) << 16);
            *(uint32_t*)(sbase + C1_A + SWZ(p * 128 + ci * 2)) = pk;
        }
    }
    CP_WAIT0();
    __syncthreads();

    int wm = (wid >> 2) * 64;
    int wn = (wid & 3) * 48;
    float acc[4][6][4];
#pragma unroll
    for (int a = 0; a < 4; a++)
#pragma unroll
        for (int b = 0; b < 6; b++)
#pragma unroll
            for (int c = 0; c < 4; c++) acc[a][b][c] = 0.0f;

#pragma unroll
    for (int kk = 0; kk < 2; kk++) {
        uint32_t bf[6][2];
#pragma unroll
        for (int bb = 0; bb < 3; bb++) {
            int r = wn + bb * 16 + ((lane >> 4) & 1) * 8 + (lane & 7);
            int kcol = kk * 16 + ((lane >> 3) & 1) * 8;
            uint32_t q0, q1, q2, q3;
            ldsm4(sb + C1_B + SWZ(r * 128 + kcol * 2), q0, q1, q2, q3);
            bf[2 * bb][0] = q0; bf[2 * bb][1] = q1;
            bf[2 * bb + 1][0] = q2; bf[2 * bb + 1][1] = q3;
        }
#pragma unroll
        for (int mi = 0; mi < 4; mi++) {
            int m_loc = wm + mi * 16 + (lane & 7) + ((lane >> 3) & 1) * 8;
            int kh = kk * 16 + (lane >> 4) * 8;
            uint32_t a0, a1, a2, a3;
            ldsm4(sb + C1_A + SWZ(m_loc * 128 + kh * 2), a0, a1, a2, a3);
#pragma unroll
            for (int ni = 0; ni < 6; ni++)
                mma16816(acc[mi][ni], a0, a1, a2, a3, bf[ni][0], bf[ni][1]);
        }
    }

    // epilogue: BN1 + ReLU6 -> padded NHWC fp16 (u32 scatter)
    __half* h1b = g_h1p + (size_t)img * PPIX * 192;
#pragma unroll
    for (int mi = 0; mi < 4; mi++) {
#pragma unroll
        for (int h = 0; h < 2; h++) {
            int m = wm + mi * 16 + (lane >> 2) + h * 8;
            int pu = pix0 + m;
            int y = pu / 112, xx = pu - y * 112;
            __half* dst = h1b + (size_t)((y + 1) * 114 + xx + 1) * 192;
#pragma unroll
            for (int ni = 0; ni < 6; ni++) {
                int c = wn + ni * 8 + 2 * (lane & 3);
                float y0 = fmaf(acc[mi][ni][h * 2 + 0], bnS[c],     bnS[192 + c]);
                float y1 = fmaf(acc[mi][ni][h * 2 + 1], bnS[c + 1], bnS[192 + c + 1]);
                y0 = fminf(fmaxf(y0, 0.0f), 6.0f);
                y1 = fminf(fmaxf(y1, 0.0f), 6.0f);
                uint32_t pk = (uint32_t)__half_as_ushort(__float2half_rn(y0)) |
                              ((uint32_t)__half_as_ushort(__float2half_rn(y1)) << 16);
                *(uint32_t*)(dst + c) = pk;
            }
        }
    }
}

// ---------------- conv2 (3x3) + conv3 (1x1) fused, 3-stage pipeline ---------
// grid (67, 16), 384 thr / 12 warps. BM=192 padded pixels, BN=192,
// K = 9 shifts x 3 chunks of 64. Warp grid 3(M) x 4(N), tile 64x48.
// 3-stage cp.async ring, ONE __syncthreads per chunk:
//   wait(chunk c ready) -> sync -> issue load(c+2) -> compute(c)
// After mainloop: BN2+ReLU6 -> SMEM h2 tile, conv3 GEMM, BN3+residual store.
#define F_BN2  0                          // 1536
#define F_BN3  1536                       // 256
#define F_W3   2048                       // 12288
#define F_A0   14336                      // 3 x 24576 = 73728
#define F_B0   (14336 + 73728)            // 3 x 24576 = 73728  (ends 161792)
#define F_H2S  14336                      // 73728, overlays A ring after mainloop
#define F_SMEM (161792 + 1024)

__global__ __launch_bounds__(384, 1) void conv23_fused(
    const float* __restrict__ g2, const float* __restrict__ b2,
    const float* __restrict__ m2, const float* __restrict__ v2,
    const float* __restrict__ g3, const float* __restrict__ b3,
    const float* __restrict__ m3, const float* __restrict__ v3,
    const float* __restrict__ x, float* __restrict__ out)
{
    extern __shared__ char dsm[];
    uint32_t sb = (smem_u32(dsm) + 1023u) & ~1023u;
    char* sbase = dsm + (sb - smem_u32(dsm));
    float* bn2 = (float*)(sbase + F_BN2);
    float* bn3 = (float*)(sbase + F_BN3);

    int tid = threadIdx.x, wid = tid >> 5, lane = tid & 31;
    int img   = blockIdx.y;
    int pbase = 115 + blockIdx.x * 192;

    // w3 -> SMEM (3 SW128 chunks of [32co x 64ci])
    for (int i = tid; i < 768; i += 384) {
        int ch = i >> 8; int rem = i & 255;
        int row = rem >> 3, c16 = rem & 7;
        CP_ASYNC16(sb + F_W3 + ch * 4096 + SWZ(row * 128 + c16 * 16),
                   (const char*)(g_w3r + row * 192 + ch * 64) + c16 * 16);
    }

    float alpha2 = g_alpha[1], alpha3 = g_alpha[2];
    for (int c = tid; c < 192; c += 384) {
        float is = rsqrtf(v2[c] + EPS);
        bn2[c]       = alpha2 * g2[c] * is;
        bn2[192 + c] = b2[c] - m2[c] * g2[c] * is;
    }
    if (tid < 32) {
        float is = rsqrtf(v3[tid] + EPS);
        bn3[tid]      = alpha3 * g3[tid] * is;
        bn3[32 + tid] = b3[tid] - m3[tid] * g3[tid] * is;
    }

    const __half* h1i = g_h1p + (size_t)img * PPIX * 192;

    auto load_chunk = [&](int chunk) {
        int sh = chunk / 3, ch = chunk - sh * 3;
        int soff = (sh / 3 - 1) * 114 + (sh % 3 - 1);
        const __half* ain = h1i + (size_t)(pbase + soff) * 192 + ch * 64;
        const __half* bw  = g_w2r + (size_t)sh * 36864 + (size_t)ch * 64;
        int st = chunk % 3;
        uint32_t sA = sb + F_A0 + st * 24576;
        uint32_t sB = sb + F_B0 + st * 24576;
#pragma unroll
        for (int p = 0; p < 4; p++) {
            int lin = p * 384 + tid;
            int row = lin >> 3, c16 = lin & 7;
            CP_ASYNC16(sA + SWZ(row * 128 + c16 * 16),
                       (const char*)(ain + (size_t)row * 192) + c16 * 16);
        }
#pragma unroll
        for (int p = 0; p < 4; p++) {
            int lin = p * 384 + tid;
            int row = lin >> 3, c16 = lin & 7;
            CP_ASYNC16(sB + SWZ(row * 128 + c16 * 16),
                       (const char*)(bw + (size_t)row * 192) + c16 * 16);
        }
    };

    int wm = (wid >> 2) * 64;     // 0,64,128
    int wn = (wid & 3) * 48;      // 0..144

    float acc[4][6][4];
#pragma unroll
    for (int a = 0; a < 4; a++)
#pragma unroll
        for (int b = 0; b < 6; b++)
#pragma unroll
            for (int c = 0; c < 4; c++) acc[a][b][c] = 0.0f;

    // prologue: 2 chunks in flight
    load_chunk(0); CP_COMMIT();
    load_chunk(1); CP_COMMIT();

    for (int c = 0; c < 27; c++) {
        if (c == 26) { CP_WAIT0(); } else { CP_WAIT1(); }
        __syncthreads();
        if (c + 2 < 27) { load_chunk(c + 2); CP_COMMIT(); }

        int st = c % 3;
        uint32_t sA = sb + F_A0 + st * 24576;
        uint32_t sB = sb + F_B0 + st * 24576;
#pragma unroll
        for (int kk = 0; kk < 4; kk++) {
            uint32_t bf[6][2];
#pragma unroll
            for (int bb = 0; bb < 3; bb++) {
                int r = wn + bb * 16 + ((lane >> 4) & 1) * 8 + (lane & 7);
                int kcol = kk * 16 + ((lane >> 3) & 1) * 8;
                uint32_t q0, q1, q2, q3;
                ldsm4(sB + SWZ(r * 128 + kcol * 2), q0, q1, q2, q3);
                bf[2 * bb][0] = q0; bf[2 * bb][1] = q1;
                bf[2 * bb + 1][0] = q2; bf[2 * bb + 1][1] = q3;
            }
#pragma unroll
            for (int mi = 0; mi < 4; mi++) {
                int m_loc = wm + mi * 16 + (lane & 7) + ((lane >> 3) & 1) * 8;
                int kh = kk * 16 + (lane >> 4) * 8;
                uint32_t a0, a1, a2, a3;
                ldsm4(sA + SWZ(m_loc * 128 + kh * 2), a0, a1, a2, a3);
#pragma unroll
                for (int ni = 0; ni < 6; ni++)
                    mma16816(acc[mi][ni], a0, a1, a2, a3, bf[ni][0], bf[ni][1]);
            }
        }
    }
    __syncthreads();   // all reads of ring done before h2s overlay

    // ---- BN2 + ReLU6 -> SMEM h2 tile (fp16, 3 SW128 chunks of 64 ci) ----
    char* h2s = sbase + F_H2S;
#pragma unroll
    for (int mi = 0; mi < 4; mi++) {
#pragma unroll
        for (int h = 0; h < 2; h++) {
            int m = wm + mi * 16 + (lane >> 2) + h * 8;
#pragma unroll
            for (int ni = 0; ni < 6; ni++) {
                int cch = wn + ni * 8 + 2 * (lane & 3);
                float y0 = fmaf(acc[mi][ni][h * 2 + 0], bn2[cch],     bn2[192 + cch]);
                float y1 = fmaf(acc[mi][ni][h * 2 + 1], bn2[cch + 1], bn2[192 + cch + 1]);
                y0 = fminf(fmaxf(y0, 0.0f), 6.0f);
                y1 = fminf(fmaxf(y1, 0.0f), 6.0f);
                uint32_t pk = (uint32_t)__half_as_ushort(__float2half_rn(y0)) |
                              ((uint32_t)__half_as_ushort(__float2half_rn(y1)) << 16);
                *(uint32_t*)(h2s + (cch >> 6) * 24576 + SWZ(m * 128 + (cch & 63) * 2)) = pk;
            }
        }
    }
    __syncthreads();

    // ---- conv3: M=192, N=32, K=192 from SMEM ----
    int wm3 = (wid >> 2) * 64;
    int wn3 = (wid & 3) * 8;
    float acc3[4][4];
#pragma unroll
    for (int a = 0; a < 4; a++)
#pragma unroll
        for (int c = 0; c < 4; c++) acc3[a][c] = 0.0f;

#pragma unroll
    for (int ch = 0; ch < 3; ch++) {
        uint32_t sA = sb + F_H2S + ch * 24576;
        uint32_t sB = sb + F_W3 + ch * 4096;
#pragma unroll
        for (int kk = 0; kk < 4; kk++) {
            uint32_t b0, b1;
            ldsm2(sB + SWZ((wn3 + (lane & 7)) * 128 +
                           (kk * 16 + ((lane >> 3) & 1) * 8) * 2), b0, b1);
#pragma unroll
            for (int mi = 0; mi < 4; mi++) {
                int m_loc = wm3 + mi * 16 + (lane & 7) + ((lane >> 3) & 1) * 8;
                int kh = kk * 16 + (lane >> 4) * 8;
                uint32_t a0, a1, a2, a3;
                ldsm4(sA + SWZ(m_loc * 128 + kh * 2), a0, a1, a2, a3);
                mma16816(acc3[mi], a0, a1, a2, a3, b0, b1);
            }
        }
    }

    // ---- BN3 + residual + masked NCHW store ----
    const float* xi = x + (size_t)img * 32 * HW;
    float* oi = out + (size_t)img * 32 * HW;
#pragma unroll
    for (int mi = 0; mi < 4; mi++) {
#pragma unroll
        for (int h = 0; h < 2; h++) {
            int m = wm3 + mi * 16 + (lane >> 2) + h * 8;
            int pp = pbase + m;
            int yp = pp / 114, xq = pp - yp * 114;
            if (yp >= 1 && yp <= 112 && xq >= 1 && xq <= 112) {
                int up = (yp - 1) * 112 + (xq - 1);
                int c = wn3 + 2 * (lane & 3);
                size_t i0 = (size_t)c * HW + up;
                size_t i1 = i0 + HW;
                oi[i0] = fmaf(acc3[mi][h * 2 + 0], bn3[c],     bn3[32 + c])     + xi[i0];
                oi[i1] = fmaf(acc3[mi][h * 2 + 1], bn3[c + 1], bn3[32 + c + 1]) + xi[i1];
            }
        }
    }
}

// ---------------- launch ----------------------------------------------------
extern "C" void kernel_launch(void* const* d_in, const int* in_sizes, int n_in,
                              void* d_out, int out_size) {
    const float* x  = (const float*)d_in[0];
    const float* w1 = (const float*)d_in[1];
    const float* g1 = (const float*)d_in[2];
    const float* b1 = (const float*)d_in[3];
    const float* m1 = (const float*)d_in[4];
    const float* v1 = (const float*)d_in[5];
    const float* w2 = (const float*)d_in[6];
    const float* g2 = (const float*)d_in[7];
    const float* b2 = (const float*)d_in[8];
    const float* m2 = (const float*)d_in[9];
    const float* v2 = (const float*)d_in[10];
    const float* w3 = (const float*)d_in[11];
    const float* g3 = (const float*)d_in[12];
    const float* b3 = (const float*)d_in[13];
    const float* m3 = (const float*)d_in[14];
    const float* v3 = (const float*)d_in[15];
    float* out = (float*)d_out;

    cudaFuncSetAttribute(conv1_mma, cudaFuncAttributeMaxDynamicSharedMemorySize, C1_SMEM);
    cudaFuncSetAttribute(conv23_fused, cudaFuncAttributeMaxDynamicSharedMemorySize, F_SMEM);

    stats_abs_all<<<dim3(148, 3), 256>>>(w1, w2, w3);
    stats_delta_all<<<3, 256>>>();
    stats_alpha_all<<<dim3(148, 3), 256>>>(w1, w2, w3);
    stats_alpha_fin_all<<<3, 256>>>();
    prep_all<<<326, 256>>>(w1, w2, w3);

    conv1_mma<<<dim3(98, 16), 256, C1_SMEM>>>(x, g1, b1, m1, v1);
    conv23_fused<<<dim3(67, 16), 384, F_SMEM>>>(g2, b2, m2, v2,
                                                g3, b3, m3, v3, x, out);
}